// round 12
// baseline (speedup 1.0000x reference)
#include <cuda_runtime.h>
#include <math.h>

// ---- problem geometry (sized generously; actual sizes come from in_sizes) ----
#define KS      20        // gaussian kernel size
#define MAX_W   4096
#define MAX_A   256
#define MAX_L   64

#define FOUR_PI 12.566370614359172f

// ---- device scratch (no allocations allowed) ----
__device__ float  g_n_unk_w[MAX_W];           // unknown-layer n at each wavelength
__device__ float  g_inv_lam[MAX_W];           // 1/lambda
__device__ float  g_s2[MAX_A];                // (n0 * sin(angle))^2
__device__ float  g_r0[MAX_A];                // first interface r
__device__ float  g_qm[MAX_A];                // q_{U-1}(a)
__device__ float  g_qp[MAX_A];                // q_{U+1}(a)
__device__ float2 g_cr[MAX_L * MAX_A];        // (coef2_k = 4*pi*d_k*q_k, r_k)
__device__ float  g_d_unk_dev;

// ============================================================================
// Prep kernel: 16 blocks x 256 threads.
//   blocks 0..7 : wavelength job (min/max, gaussian conv on the fly, interp)
//   blocks 8..15: angle tables, one task per (layer k, angle a)
// ============================================================================
__global__ void prep_kernel(const float* __restrict__ nk, int NP,
                            const float* __restrict__ d_unk,
                            const float* __restrict__ ta, int LA,
                            const float* __restrict__ tb, int LB,
                            const float* __restrict__ fn,
                            const float* __restrict__ wl, int W,
                            const float* __restrict__ ang, int A)
{
    const int bid = blockIdx.x, tid = threadIdx.x;
    const int L = LA + LB + 3;
    const int U = LA + 1;

    if (bid < 8) {
        // ---- wavelength job ----
        __shared__ float rmin[256], rmax[256];
        float vmin = 3.0e38f, vmax = -3.0e38f;
        for (int i = tid; i < W; i += 256) {
            float x = wl[i];
            vmin = fminf(vmin, x);
            vmax = fmaxf(vmax, x);
        }
        rmin[tid] = vmin; rmax[tid] = vmax; __syncthreads();
        for (int o = 128; o > 0; o >>= 1) {
            if (tid < o) {
                rmin[tid] = fminf(rmin[tid], rmin[tid + o]);
                rmax[tid] = fmaxf(rmax[tid], rmax[tid + o]);
            }
            __syncthreads();
        }
        const float wmin = rmin[0], wmax = rmax[0];

        // gaussian weights in registers (AMPLITUDE cancels in normalization)
        float kw[KS]; float s = 0.f;
        #pragma unroll
        for (int i = 0; i < KS; ++i) {
            float x = -10.f + (20.f / 19.f) * (float)i;
            kw[i] = expf(-x * x * (1.f / 32.f));       // sigma = 4
            s += kw[i];
        }
        float inv = 1.f / s;
        #pragma unroll
        for (int i = 0; i < KS; ++i) kw[i] *= inv;

        const int NS = NP - KS + 1;
        const float invh = (float)(NS - 1) / (wmax - wmin);
        for (int w = bid * 256 + tid; w < W; w += 8 * 256) {
            float lam = wl[w];
            float tp = fminf(fmaxf((lam - wmin) * invh, 0.f), (float)(NS - 1));
            int i0 = min((int)tp, NS - 2);
            float f = tp - (float)i0;
            float a0 = 0.f, a1 = 0.f;
            #pragma unroll
            for (int j = 0; j < KS; ++j) a0 = fmaf(nk[i0 + j], kw[j], a0);
            #pragma unroll
            for (int j = 0; j < KS; ++j) a1 = fmaf(nk[i0 + 1 + j], kw[j], a1);
            g_n_unk_w[w] = a0 + f * (a1 - a0);
            g_inv_lam[w] = 1.0f / lam;
        }
        if (bid == 0 && tid == 0) g_d_unk_dev = d_unk[0];
    } else {
        // ---- angle-table job: task = (k in 1..L-2) x (a in 0..A-1) ----
        const float n0 = fn[0];
        const int ntask = (L - 2) * A;
        for (int idx = (bid - 8) * 256 + tid; idx < ntask; idx += 8 * 256) {
            int k = 1 + idx / A;
            int a = idx - (k - 1) * A;
            float sa = sinf(ang[a]);
            float sv = n0 * sa;
            float s2 = sv * sv;

            // q of fixed layer j (j != U)
            #define QOF(j) sqrtf(fmaxf(fn[(j) < U ? (j) : (j) - 1] * fn[(j) < U ? (j) : (j) - 1] - s2, 0.f))

            float coef2 = 0.f, r = 0.f;
            if (k != U) {
                int di = k - 1;
                float d = (di < LA) ? ta[di] : tb[di - LA - 1];
                float qk = QOF(k);
                coef2 = FOUR_PI * d * qk;              // 2*delta coefficient
                if (k != U - 1) {
                    float qn = QOF(k + 1);
                    r = (qk - qn) / (qk + qn);
                }
            }
            g_cr[k * MAX_A + a] = make_float2(coef2, r);

            if (k == 1) {
                g_s2[a] = s2;
                float q0 = QOF(0), q1 = QOF(1);
                g_r0[a] = (q0 - q1) / (q0 + q1);
            }
            if (k == U - 1) g_qm[a] = QOF(U - 1);
            if (k == U + 1) g_qp[a] = QOF(U + 1);
            #undef QOF
        }
    }
}

// ============================================================================
// TMM step with global phase factored out:
//   t  = A * e^{-2i delta}
//   A' = t + r*B ; B' = r*t + B       (global phase cancels in R = |B|^2/|A|^2)
// ============================================================================
__device__ __forceinline__ void tmm_step(float& Ar, float& Ai, float& Br, float& Bi,
                                         float ang2, float r)
{
    float sn, cs;
    __sincosf(ang2, &sn, &cs);
    float tr = fmaf(Ar, cs,  Ai * sn);
    float ti = fmaf(Ai, cs, -Ar * sn);
    float nAr = fmaf(r, Br, tr);
    float nAi = fmaf(r, Bi, ti);
    Br = fmaf(r, tr, Br);
    Bi = fmaf(r, ti, Bi);
    Ar = nAr; Ai = nAi;
}

// ============================================================================
// Specialized main kernel: ONE pixel per thread, branch-free segments.
// Grid = W blocks x A threads -> 2048 blocks: ~14 blocks/SM, occupancy-driven
// latency hiding instead of per-thread ILP. Low register footprint.
// ============================================================================
template<int LAc, int LBc>
__global__ void __launch_bounds__(128)
tmm_kernel_t(int W, int A, float* __restrict__ out)
{
    constexpr int L = LAc + LBc + 3;
    constexpr int U = LAc + 1;
    const int a = threadIdx.x;
    const int w = blockIdx.x;

    const float invl = g_inv_lam[w];
    const float s2   = g_s2[a];
    const float nu   = g_n_unk_w[w];
    const float qu   = sqrtf(fmaxf(fmaf(nu, nu, -s2), 0.f));
    const float qm   = g_qm[a];
    const float qp   = g_qp[a];
    const float rA   = (qm - qu) / (qm + qu);          // interface U-1
    const float rB   = (qu - qp) / (qu + qp);          // interface U
    const float dU   = FOUR_PI * g_d_unk_dev * qu * invl;

    const float r0 = g_r0[a];
    float Ar = 1.f, Ai = 0.f, Br = r0, Bi = 0.f;

    const float2* __restrict__ cr = &g_cr[a];

    // segment 1: k = 1 .. U-2, pure table steps (no branches)
    #pragma unroll 7
    for (int k = 1; k <= U - 2; ++k) {
        float2 c = cr[k * MAX_A];
        tmm_step(Ar, Ai, Br, Bi, c.x * invl, c.y);
    }
    // k = U-1: table coef, per-pixel rA
    {
        float2 c = cr[(U - 1) * MAX_A];
        tmm_step(Ar, Ai, Br, Bi, c.x * invl, rA);
    }
    // k = U: unknown layer
    tmm_step(Ar, Ai, Br, Bi, dU, rB);
    // segment 2: k = U+1 .. L-2, pure table steps
    #pragma unroll 5
    for (int k = U + 1; k <= L - 2; ++k) {
        float2 c = cr[k * MAX_A];
        tmm_step(Ar, Ai, Br, Bi, c.x * invl, c.y);
    }

    out[w * A + a] = fmaf(Br, Br, Bi * Bi) / fmaf(Ar, Ar, Ai * Ai);
}

// ============================================================================
// Generic fallback: one pixel per thread, runtime loop.
// ============================================================================
__global__ void tmm_kernel_g(int W, int A, int LA, int LB, float* __restrict__ out)
{
    const int a = threadIdx.x;
    const int w = blockIdx.x;
    if (a >= A) return;
    const int L = LA + LB + 3;
    const int U = LA + 1;

    const float invl = g_inv_lam[w];
    const float s2 = g_s2[a];
    const float nu = g_n_unk_w[w];
    const float qu = sqrtf(fmaxf(fmaf(nu, nu, -s2), 0.f));
    const float qm = g_qm[a];
    const float qp = g_qp[a];
    const float rA = (qm - qu) / (qm + qu);
    const float rB = (qu - qp) / (qu + qp);
    const float dU = FOUR_PI * g_d_unk_dev * qu * invl;

    const float r0 = g_r0[a];
    float Ar = 1.f, Ai = 0.f, Br = r0, Bi = 0.f;

    for (int k = 1; k <= L - 2; ++k) {
        float ang2, r;
        if (k == U) { ang2 = dU; r = rB; }
        else {
            float2 c = g_cr[k * MAX_A + a];
            ang2 = c.x * invl;
            r = (k == U - 1) ? rA : c.y;
        }
        tmm_step(Ar, Ai, Br, Bi, ang2, r);
    }
    out[w * A + a] = fmaf(Br, Br, Bi * Bi) / fmaf(Ar, Ar, Ai * Ai);
}

// ============================================================================
extern "C" void kernel_launch(void* const* d_in, const int* in_sizes, int n_in,
                              void* d_out, int out_size)
{
    const float* nk  = (const float*)d_in[0];   // refractive_index [NP]
    const float* dun = (const float*)d_in[1];   // unknown_layer_thickness [1]
    const float* ta  = (const float*)d_in[2];   // thickness_above [LA]
    const float* tb  = (const float*)d_in[3];   // thickness_below [LB]
    const float* fn  = (const float*)d_in[4];   // fixed_n [LA+LB+2]
    const float* wl  = (const float*)d_in[5];   // wavelengths [W]
    const float* ang = (const float*)d_in[6];   // angles [A]

    const int NP = in_sizes[0];
    const int LA = in_sizes[2];
    const int LB = in_sizes[3];
    const int W  = in_sizes[5];
    const int A  = in_sizes[6];
    float* out = (float*)d_out;

    prep_kernel<<<16, 256>>>(nk, NP, dun, ta, LA, tb, LB, fn, wl, W, ang, A);

    if (LA == 15 && LB == 15) {
        tmm_kernel_t<15, 15><<<W, A>>>(W, A, out);
    } else {
        tmm_kernel_g<<<W, A>>>(W, A, LA, LB, out);
    }
}